// round 9
// baseline (speedup 1.0000x reference)
#include <cuda_runtime.h>
#include <cuda_fp16.h>
#include <cstdint>

#define N_ENT    100000
#define N_REL    250000
#define N_TRIG   50000
#define N_ARGS   250000
#define ENT_DIM  288
#define REL_R    256
#define RTYPE_DIM 32
#define ROLE_DIM 256
#define ARG_DIM  576
#define KDIM     1152
#define OUT_DIM  544

#define NKEY     (N_TRIG * 2)       // 100000 (trig, side) segments
#define BLK_KEYS 1024
#define NBLK     ((NKEY + BLK_KEYS - 1) / BLK_KEYS)   // 98
#define NKEY_PAD (NBLK * BLK_KEYS)                    // 100352

// Scratch
__device__ __half g_Wh[(size_t)ROLE_DIM * KDIM]; // 0.59 MB: Wcat^T [256,1152] fp16
__device__ int    g_cnt[NKEY_PAD];
__device__ int    g_off[NKEY + 1];
__device__ int    g_cur[NKEY];
__device__ int    g_part[NBLK];
__device__ int    g_ppre[NBLK + 1];
__device__ int4   g_rec[N_ARGS];                 // {rel, ent, rtype, 0} sorted by key

// ---------------------------------------------------------------------------
// helpers
// ---------------------------------------------------------------------------
__device__ __forceinline__ void mma_f16(float* c, const uint32_t* a, const uint32_t* b) {
    asm volatile(
        "mma.sync.aligned.m16n8k16.row.col.f32.f16.f16.f32 "
        "{%0,%1,%2,%3}, {%4,%5,%6,%7}, {%8,%9}, {%0,%1,%2,%3};"
        : "+f"(c[0]), "+f"(c[1]), "+f"(c[2]), "+f"(c[3])
        : "r"(a[0]), "r"(a[1]), "r"(a[2]), "r"(a[3]), "r"(b[0]), "r"(b[1]));
}
__device__ __forceinline__ void cpa16(uint32_t s, const void* g) {
    asm volatile("cp.async.cg.shared.global [%0], [%1], 16;" :: "r"(s), "l"(g));
}
__device__ __forceinline__ uint32_t smem_u32(const void* p) {
    uint32_t a;
    asm("{ .reg .u64 t; cvta.to.shared.u64 t, %1; cvt.u32.u64 %0, t; }"
        : "=r"(a) : "l"(p));
    return a;
}

// ---------------------------------------------------------------------------
// Wh[n][k] = half( k < 576 ? W_in[k][n] : W_out[k-576][n] )
// ---------------------------------------------------------------------------
__global__ void __launch_bounds__(128) transpose_W(
    const float* __restrict__ W_in, const float* __restrict__ W_out)
{
    const int n = blockIdx.x;  // 0..255
    for (int k = threadIdx.x; k < KDIM; k += 128) {
        float w = (k < ARG_DIM) ? __ldg(W_in  + (size_t)k * ROLE_DIM + n)
                                : __ldg(W_out + (size_t)(k - ARG_DIM) * ROLE_DIM + n);
        g_Wh[(size_t)n * KDIM + k] = __float2half_rn(w);
    }
}

// ---------------------------------------------------------------------------
// CSR build: zero -> histogram -> 3-phase parallel scan -> fill
// ---------------------------------------------------------------------------
__global__ void __launch_bounds__(256) zero_cnt() {
    int i = blockIdx.x * 256 + threadIdx.x;
    if (i < NKEY_PAD) g_cnt[i] = 0;
}

__global__ void __launch_bounds__(256) hist_args(
    const int* __restrict__ arg_trig, const int* __restrict__ arg_is_in)
{
    int i = blockIdx.x * 256 + threadIdx.x;
    if (i >= N_ARGS) return;
    atomicAdd(&g_cnt[arg_trig[i] * 2 + arg_is_in[i]], 1);
}

__global__ void __launch_bounds__(256) scan_local()
{
    __shared__ int wsum[8];
    const int tid  = threadIdx.x;
    const int lane = tid & 31;
    const int warp = tid >> 5;
    const int i0   = blockIdx.x * BLK_KEYS + tid * 4;

    int4 v = *reinterpret_cast<const int4*>(g_cnt + i0);
    const int s4 = v.x + v.y + v.z + v.w;
    int inc = s4;
    #pragma unroll
    for (int d = 1; d < 32; d <<= 1) {
        int t = __shfl_up_sync(0xFFFFFFFFu, inc, d);
        if (lane >= d) inc += t;
    }
    if (lane == 31) wsum[warp] = inc;
    __syncthreads();
    int wpre = 0;
    if (warp > 0) {
        #pragma unroll
        for (int j = 0; j < 7; j++) if (j < warp) wpre += wsum[j];
    }
    const int excl = wpre + inc - s4;
    const int o0 = excl, o1 = o0 + v.x, o2 = o1 + v.y, o3 = o2 + v.z;
    if (i0 + 0 < NKEY) g_off[i0 + 0] = o0;
    if (i0 + 1 < NKEY) g_off[i0 + 1] = o1;
    if (i0 + 2 < NKEY) g_off[i0 + 2] = o2;
    if (i0 + 3 < NKEY) g_off[i0 + 3] = o3;
    if (tid == 255) g_part[blockIdx.x] = wpre + inc;
}

__global__ void __launch_bounds__(32) scan_part()
{
    const int lane = threadIdx.x;
    int v[4];
    int s4 = 0;
    #pragma unroll
    for (int j = 0; j < 4; j++) {
        const int i = lane * 4 + j;
        v[j] = (i < NBLK) ? g_part[i] : 0;
        s4 += v[j];
    }
    int inc = s4;
    #pragma unroll
    for (int d = 1; d < 32; d <<= 1) {
        int t = __shfl_up_sync(0xFFFFFFFFu, inc, d);
        if (lane >= d) inc += t;
    }
    int run = inc - s4;
    #pragma unroll
    for (int j = 0; j < 4; j++) {
        const int i = lane * 4 + j;
        if (i < NBLK) g_ppre[i] = run;
        run += v[j];
    }
    if (lane == 31) g_off[NKEY] = inc;
}

__global__ void __launch_bounds__(256) scan_add()
{
    const int add = g_ppre[blockIdx.x];
    const int i0  = blockIdx.x * BLK_KEYS + threadIdx.x * 4;
    #pragma unroll
    for (int j = 0; j < 4; j++) {
        const int i = i0 + j;
        if (i < NKEY) {
            const int o = g_off[i] + add;
            g_off[i] = o;
            g_cur[i] = o;
        }
    }
}

__global__ void __launch_bounds__(256) fill_args(
    const int* __restrict__ arg_trig, const int* __restrict__ arg_rel,
    const int* __restrict__ arg_ent, const int* __restrict__ arg_is_in,
    const int* __restrict__ rtype_ids)
{
    int i = blockIdx.x * 256 + threadIdx.x;
    if (i >= N_ARGS) return;
    const int key = arg_trig[i] * 2 + arg_is_in[i];
    const int r   = arg_rel[i];
    const int pos = atomicAdd(&g_cur[key], 1);
    g_rec[pos] = make_int4(r, arg_ent[i], __ldg(rtype_ids + r), 0);
}

// ---------------------------------------------------------------------------
// Trigger entity embedding -> out[:, 0:288]
// ---------------------------------------------------------------------------
__global__ void __launch_bounds__(256) copy_trig(
    const float* __restrict__ ent, const int* __restrict__ trig_ent_id,
    float* __restrict__ out)
{
    const int w    = (blockIdx.x * 256 + threadIdx.x) >> 5;
    const int lane = threadIdx.x & 31;
    if (w >= N_TRIG) return;
    const float4* src = reinterpret_cast<const float4*>(
        ent + (size_t)__ldg(trig_ent_id + w) * ENT_DIM);
    float4* dst = reinterpret_cast<float4*>(out + (size_t)w * OUT_DIM);
    dst[lane]      = src[lane];
    dst[lane + 32] = src[lane + 32];
    if (lane < 8) dst[lane + 64] = src[lane + 64];
}

// ---------------------------------------------------------------------------
// FUSED aggregate + GEMM per 64-trigger tile.
// Phase 1: 16 warps aggregate 128 (trig,side) keys into the fp16 S-tile in smem.
// Phase 2: C[64,256] = St @ Wh^T via mma.m16n8k16, A from smem, B cp.async.
// ---------------------------------------------------------------------------
#define FBM   64
#define FBK   32
#define LDS_S 1160                       // halves per S-tile row (1152 + 8 pad)
#define LDB   40                         // halves per B row (32 + 8 pad)
#define S_TILE_H (FBM * LDS_S)           // 74240 halves = 148480 B
#define B_BUF_H  (ROLE_DIM * LDB)        // 10240 halves = 20480 B
#define FSM_TOTAL ((S_TILE_H + 2 * B_BUF_H) * 2)  // 189440 B
#define FNKCH (KDIM / FBK)               // 36

__global__ void __launch_bounds__(512, 1) fused_ag_gemm(
    const float* __restrict__ ent, const float* __restrict__ rel,
    const float* __restrict__ rtt, float* __restrict__ out)
{
    extern __shared__ __align__(1024) __half smem[];
    __half* St = smem;                   // [64][LDS_S]
    __half* Bs = smem + S_TILE_H;        // [2][256][LDB]
    const uint32_t sbB = smem_u32(Bs);

    const int tid  = threadIdx.x;
    const int wid  = tid >> 5;           // 0..15
    const int lane = tid & 31;
    const int m0   = blockIdx.x * FBM;

    // ---------------- Phase 1: aggregate into smem S-tile ----------------
    const bool lo8 = lane < 8;
    #pragma unroll 1
    for (int i = 0; i < 8; i++) {
        const int kl  = wid * 8 + i;       // 0..127 (local key)
        const int key = 2 * m0 + kl;
        if (key >= NKEY) break;

        const int off = __ldg(g_off + key);
        const int end = __ldg(g_off + key + 1);

        const float4 z = make_float4(0.f, 0.f, 0.f, 0.f);
        float4 aR0 = z, aR1 = z, aT = z, aE0 = z, aE1 = z, aE2 = z;

        for (int p = off; p < end; p++) {
            const int4 rec = __ldg(g_rec + p);
            const float4* relp = reinterpret_cast<const float4*>(rel + (size_t)rec.x * REL_R);
            const float4* entp = reinterpret_cast<const float4*>(ent + (size_t)rec.y * ENT_DIM);
            const float4* rtp  = reinterpret_cast<const float4*>(rtt + (size_t)rec.z * RTYPE_DIM);

            const float4 r0 = __ldg(relp + lane);
            const float4 r1 = __ldg(relp + lane + 32);
            const float4 e0 = __ldg(entp + lane);
            const float4 e1 = __ldg(entp + lane + 32);
            float4 t0 = z, e2 = z;
            if (lo8) { t0 = __ldg(rtp + lane); e2 = __ldg(entp + lane + 64); }

            aR0.x += r0.x; aR0.y += r0.y; aR0.z += r0.z; aR0.w += r0.w;
            aR1.x += r1.x; aR1.y += r1.y; aR1.z += r1.z; aR1.w += r1.w;
            aT.x  += t0.x; aT.y  += t0.y; aT.z  += t0.z; aT.w  += t0.w;
            aE0.x += e0.x; aE0.y += e0.y; aE0.z += e0.z; aE0.w += e0.w;
            aE1.x += e1.x; aE1.y += e1.y; aE1.z += e1.z; aE1.w += e1.w;
            aE2.x += e2.x; aE2.y += e2.y; aE2.z += e2.z; aE2.w += e2.w;
        }

        const int row = kl >> 1;
        __half2* d2 = reinterpret_cast<__half2*>(
            St + (size_t)row * LDS_S + ((kl & 1) ? 0 : ARG_DIM));
        d2[2 * lane + 0]       = __floats2half2_rn(aR0.x, aR0.y);
        d2[2 * lane + 1]       = __floats2half2_rn(aR0.z, aR0.w);
        d2[64 + 2 * lane + 0]  = __floats2half2_rn(aR1.x, aR1.y);
        d2[64 + 2 * lane + 1]  = __floats2half2_rn(aR1.z, aR1.w);
        d2[144 + 2 * lane + 0] = __floats2half2_rn(aE0.x, aE0.y);
        d2[144 + 2 * lane + 1] = __floats2half2_rn(aE0.z, aE0.w);
        d2[208 + 2 * lane + 0] = __floats2half2_rn(aE1.x, aE1.y);
        d2[208 + 2 * lane + 1] = __floats2half2_rn(aE1.z, aE1.w);
        if (lo8) {
            d2[128 + 2 * lane + 0] = __floats2half2_rn(aT.x, aT.y);
            d2[128 + 2 * lane + 1] = __floats2half2_rn(aT.z, aT.w);
            d2[272 + 2 * lane + 0] = __floats2half2_rn(aE2.x, aE2.y);
            d2[272 + 2 * lane + 1] = __floats2half2_rn(aE2.z, aE2.w);
        }
    }
    __syncthreads();

    // ---------------- Phase 2: GEMM from smem ----------------
    const int wm = wid & 1;     // 2 M-groups of 32
    const int wn = wid >> 1;    // 8 N-groups of 32
    const int qr = lane >> 2;
    const int qc = lane & 3;

    float acc[2][4][4];
    #pragma unroll
    for (int mi = 0; mi < 2; mi++)
        #pragma unroll
        for (int nj = 0; nj < 4; nj++)
            #pragma unroll
            for (int q = 0; q < 4; q++) acc[mi][nj][q] = 0.f;

    auto load_B = [&](int c, int buf) {
        const int k0 = c * FBK;
        const uint32_t bB = sbB + buf * (B_BUF_H * 2);
        #pragma unroll
        for (int j = 0; j < 2; j++) {
            const int idx = tid + j * 512;       // 0..1023
            const int row = idx >> 2, seg = idx & 3;
            cpa16(bB + (uint32_t)(row * (LDB * 2) + seg * 16),
                  g_Wh + (size_t)row * KDIM + k0 + seg * 8);
        }
        asm volatile("cp.async.commit_group;" ::: "memory");
    };

    load_B(0, 0);
    load_B(1, 1);

    for (int c = 0; c < FNKCH; c++) {
        const int buf = c & 1;
        if (c + 2 < FNKCH) asm volatile("cp.async.wait_group 1;" ::: "memory");
        else               asm volatile("cp.async.wait_group 0;" ::: "memory");
        __syncthreads();

        const __half* B = Bs + buf * B_BUF_H;
        const int k0 = c * FBK;

        #pragma unroll
        for (int ks = 0; ks < 2; ks++) {
            const int kk = ks * 16;
            uint32_t a[2][4];
            #pragma unroll
            for (int mi = 0; mi < 2; mi++) {
                const int r = wm * 32 + mi * 16 + qr;
                const __half* Ar = St + (size_t)r * LDS_S + k0 + kk + 2 * qc;
                a[mi][0] = *reinterpret_cast<const uint32_t*>(Ar);
                a[mi][1] = *reinterpret_cast<const uint32_t*>(Ar + 8 * LDS_S);
                a[mi][2] = *reinterpret_cast<const uint32_t*>(Ar + 8);
                a[mi][3] = *reinterpret_cast<const uint32_t*>(Ar + 8 * LDS_S + 8);
            }
            uint32_t b[4][2];
            #pragma unroll
            for (int nj = 0; nj < 4; nj++) {
                const int cb = wn * 32 + nj * 8 + qr;
                b[nj][0] = *reinterpret_cast<const uint32_t*>(&B[cb * LDB + kk + 2 * qc]);
                b[nj][1] = *reinterpret_cast<const uint32_t*>(&B[cb * LDB + kk + 8 + 2 * qc]);
            }
            #pragma unroll
            for (int mi = 0; mi < 2; mi++)
                #pragma unroll
                for (int nj = 0; nj < 4; nj++)
                    mma_f16(acc[mi][nj], a[mi], b[nj]);
        }
        __syncthreads();
        if (c + 2 < FNKCH) load_B(c + 2, buf);
    }

    // Epilogue: out[m, 288 + n]
    #pragma unroll
    for (int mi = 0; mi < 2; mi++) {
        const int m_lo = m0 + wm * 32 + mi * 16 + qr;
        #pragma unroll
        for (int nj = 0; nj < 4; nj++) {
            const int n = ENT_DIM + wn * 32 + nj * 8 + qc * 2;
            if (m_lo < N_TRIG)
                *reinterpret_cast<float2*>(out + (size_t)m_lo * OUT_DIM + n) =
                    make_float2(acc[mi][nj][0], acc[mi][nj][1]);
            if (m_lo + 8 < N_TRIG)
                *reinterpret_cast<float2*>(out + (size_t)(m_lo + 8) * OUT_DIM + n) =
                    make_float2(acc[mi][nj][2], acc[mi][nj][3]);
        }
    }
}

// ---------------------------------------------------------------------------
extern "C" void kernel_launch(void* const* d_in, const int* in_sizes, int n_in,
                              void* d_out, int out_size)
{
    const float* ent       = (const float*)d_in[0];
    const float* rel       = (const float*)d_in[1];
    const float* rtt       = (const float*)d_in[2];
    const float* W_in      = (const float*)d_in[3];
    const float* W_out     = (const float*)d_in[4];
    const int*   rtype_ids = (const int*)d_in[5];
    const int*   trig_ent  = (const int*)d_in[6];
    const int*   arg_trig  = (const int*)d_in[7];
    const int*   arg_rel   = (const int*)d_in[8];
    const int*   arg_ent   = (const int*)d_in[9];
    const int*   arg_is_in = (const int*)d_in[10];
    float* out = (float*)d_out;

    (void)in_sizes; (void)n_in; (void)out_size;

    zero_cnt<<<(NKEY_PAD + 255) / 256, 256>>>();
    hist_args<<<(N_ARGS + 255) / 256, 256>>>(arg_trig, arg_is_in);
    scan_local<<<NBLK, 256>>>();
    scan_part<<<1, 32>>>();
    scan_add<<<NBLK, 256>>>();
    fill_args<<<(N_ARGS + 255) / 256, 256>>>(
        arg_trig, arg_rel, arg_ent, arg_is_in, rtype_ids);
    transpose_W<<<ROLE_DIM, 128>>>(W_in, W_out);
    copy_trig<<<(N_TRIG * 32 + 255) / 256, 256>>>(ent, trig_ent, out);

    cudaFuncSetAttribute(fused_ag_gemm,
                         cudaFuncAttributeMaxDynamicSharedMemorySize, FSM_TOTAL);
    fused_ag_gemm<<<(N_TRIG + FBM - 1) / FBM, 512, FSM_TOTAL>>>(ent, rel, rtt, out);
}